// round 3
// baseline (speedup 1.0000x reference)
#include <cuda_runtime.h>

// ReadGate: q = emb[query]@qW.T + qb ; sims = <q, memory[b,m]>/8 ; w = softmax(sims)
// pooled = sum_m w*memory[b,m] ; out = pooled@oW.T + ob
// Single-pass streaming, no-max softmax (|sims/8| <~ 5, exp safe in fp32).
// Ping-pong double-buffered loads (no copies, no over-fetch past the last tile).

constexpr int Bn = 2048;
constexpr int Mn = 2048;
constexpr int Dn = 64;
constexpr int Vn = 64;
constexpr int THREADS = 256;
constexpr int NHW = 16;      // half-warps per CTA
constexpr int UNROLL = 4;    // m-rows per half-warp per iter
constexpr int ITERS = Mn / (NHW * UNROLL);   // 32

__device__ __forceinline__
void load_tile(float4 v[UNROLL], const float4* __restrict__ mrow, int it, int hw)
{
    #pragma unroll
    for (int j = 0; j < UNROLL; ++j)
        v[j] = __ldcs(mrow + (size_t)(hw + it * (NHW * UNROLL) + j * NHW) * (Dn / 4));
}

__device__ __forceinline__
void consume_tile(const float4 v[UNROLL],
                  float q0, float q1, float q2, float q3,
                  float& rsum, float& a0, float& a1, float& a2, float& a3)
{
    #pragma unroll
    for (int j = 0; j < UNROLL; ++j) {
        float s = fmaf(v[j].x, q0, fmaf(v[j].y, q1, fmaf(v[j].z, q2, v[j].w * q3)));
        s += __shfl_xor_sync(0xffffffffu, s, 8);
        s += __shfl_xor_sync(0xffffffffu, s, 4);
        s += __shfl_xor_sync(0xffffffffu, s, 2);
        s += __shfl_xor_sync(0xffffffffu, s, 1);
        const float p = __expf(s * 0.125f);
        rsum += p;
        a0 = fmaf(p, v[j].x, a0);
        a1 = fmaf(p, v[j].y, a1);
        a2 = fmaf(p, v[j].z, a2);
        a3 = fmaf(p, v[j].w, a3);
    }
}

__global__ __launch_bounds__(THREADS, 1)
void readgate_kernel(const int* __restrict__ query,
                     const float* __restrict__ memory,
                     const float* __restrict__ emb,
                     const float* __restrict__ qW,
                     const float* __restrict__ qb,
                     const float* __restrict__ oW,
                     const float* __restrict__ ob,
                     float* __restrict__ out)
{
    __shared__ float w_sh[Dn * 65];          // staged qW, then reused for oW (pad 65)
    __shared__ float e_sh[Dn];
    __shared__ float q_sh[Dn];               // q vector, then normalized pooled
    __shared__ float pooled_sh[NHW][Dn];
    __shared__ float sum_sh[NHW];

    const int b   = blockIdx.x;
    const int tid = threadIdx.x;

    // ---- stage qW (padded, conflict-free) + emb row ----
    #pragma unroll
    for (int i = tid; i < Dn * Dn; i += THREADS)
        w_sh[(i >> 6) * 65 + (i & 63)] = qW[i];
    if (tid < Dn)
        e_sh[tid] = emb[query[b] * Dn + tid];
    __syncthreads();

    // ---- q[d] = qb[d] + sum_k e[k]*qW[d,k] ----
    if (tid < Dn) {
        float acc = qb[tid];
        #pragma unroll
        for (int k = 0; k < Dn; ++k)
            acc = fmaf(e_sh[k], w_sh[tid * 65 + k], acc);
        q_sh[tid] = acc;
    }
    __syncthreads();

    // ---- stage oW now; post-mainloop barrier orders it before use ----
    #pragma unroll
    for (int i = tid; i < Dn * Dn; i += THREADS)
        w_sh[(i >> 6) * 65 + (i & 63)] = oW[i];

    // ---- main streaming loop ----
    const int hw   = tid >> 4;   // 0..15
    const int lane = tid & 15;   // 0..15
    const float q0 = q_sh[lane * 4 + 0];
    const float q1 = q_sh[lane * 4 + 1];
    const float q2 = q_sh[lane * 4 + 2];
    const float q3 = q_sh[lane * 4 + 3];

    const float4* __restrict__ mrow =
        reinterpret_cast<const float4*>(memory + (size_t)b * (Mn * Dn)) + lane;

    float rsum = 0.f;
    float a0 = 0.f, a1 = 0.f, a2 = 0.f, a3 = 0.f;

    float4 va[UNROLL], vb[UNROLL];
    load_tile(va, mrow, 0, hw);

    #pragma unroll 1
    for (int it = 0; it < ITERS - 2; it += 2) {
        load_tile(vb, mrow, it + 1, hw);
        consume_tile(va, q0, q1, q2, q3, rsum, a0, a1, a2, a3);
        load_tile(va, mrow, it + 2, hw);
        consume_tile(vb, q0, q1, q2, q3, rsum, a0, a1, a2, a3);
    }
    // epilogue: it = ITERS-2, ITERS-1 (no over-fetch)
    load_tile(vb, mrow, ITERS - 1, hw);
    consume_tile(va, q0, q1, q2, q3, rsum, a0, a1, a2, a3);
    consume_tile(vb, q0, q1, q2, q3, rsum, a0, a1, a2, a3);

    pooled_sh[hw][lane * 4 + 0] = a0;
    pooled_sh[hw][lane * 4 + 1] = a1;
    pooled_sh[hw][lane * 4 + 2] = a2;
    pooled_sh[hw][lane * 4 + 3] = a3;
    if (lane == 0) sum_sh[hw] = rsum;
    __syncthreads();

    // ---- combine partials; normalize pooled ----
    if (tid < Dn) {
        float gsum = 0.f, pl = 0.f;
        #pragma unroll
        for (int p = 0; p < NHW; ++p) {
            gsum += sum_sh[p];
            pl   += pooled_sh[p][tid];
        }
        q_sh[tid] = pl / gsum;
    }
    __syncthreads();

    // ---- out[b,v] = ob[v] + sum_d pooled[d]*oW[v,d] ----
    if (tid < Vn) {
        float acc = ob[tid];
        #pragma unroll
        for (int d = 0; d < Dn; ++d)
            acc = fmaf(q_sh[d], w_sh[tid * 65 + d], acc);
        out[(size_t)b * Vn + tid] = acc;
    }
}

extern "C" void kernel_launch(void* const* d_in, const int* in_sizes, int n_in,
                              void* d_out, int out_size)
{
    const int*   query  = (const int*)  d_in[0];
    const float* memory = (const float*)d_in[1];
    const float* emb    = (const float*)d_in[2];
    const float* qW     = (const float*)d_in[3];
    const float* qb     = (const float*)d_in[4];
    const float* oW     = (const float*)d_in[5];
    const float* ob     = (const float*)d_in[6];
    float* out = (float*)d_out;

    readgate_kernel<<<Bn, THREADS>>>(query, memory, emb, qW, qb, oW, ob, out);
}